// round 5
// baseline (speedup 1.0000x reference)
#include <cuda_runtime.h>
#include <cstdint>
#include <cstddef>

// Problem constants
#define NB  128
#define NR  500
#define NN  500
#define NK  10
#define NE  128
#define NH1 640
#define NKE 1280
#define NM  (NB * NR)       // 64000 rows

// Scratch (static device arrays)
__device__ float g_encr[(size_t)NB * NN * NE];  // tf32-rounded enc (32.8 MB)
__device__ float g_mean[(size_t)NM * NE];       // tf32-rounded pad mean  (32.8 MB)
__device__ int   g_sel[(size_t)NM * NK];        // selected node ids (2.56 MB)
__device__ float g_w1[NH1 * NKE];               // tf32-rounded
__device__ float g_w2[NE * NH1];                // tf32-rounded

__device__ __forceinline__ float f2tf_f(float x) {
    uint32_t u;
    asm("cvt.rna.tf32.f32 %0, %1;" : "=r"(u) : "f"(x));
    return __uint_as_float(u);
}

// ---------------------------------------------------------------------------
// Kernel 0: tf32-round enc, w1, w2
// ---------------------------------------------------------------------------
__global__ void __launch_bounds__(256) cvt_kernel(
    const float* __restrict__ enc,
    const float* __restrict__ w1, const float* __restrict__ w2)
{
    int i = blockIdx.x * 256 + threadIdx.x;
    if (i < NB * NN * NE) g_encr[i] = f2tf_f(enc[i]);
    if (i < NH1 * NKE)    g_w1[i]   = f2tf_f(w1[i]);
    if (i < NE * NH1)     g_w2[i]   = f2tf_f(w2[i]);
}

// ---------------------------------------------------------------------------
// Kernel 1: top-K nearest unvisited -> g_sel; pad mean -> g_mean
// One warp per (b, r) row. 4 warps / block.
// ---------------------------------------------------------------------------
__global__ void __launch_bounds__(128) prep_kernel(
    const int*   __restrict__ current,
    const float* __restrict__ distance,
    const float* __restrict__ masked,
    const float* __restrict__ enc)
{
    const int row  = blockIdx.x * 4 + (threadIdx.x >> 5);
    const int lane = threadIdx.x & 31;
    const int b    = row / NR;
    const uint32_t INFB = 0x7f800000u;
    const float FINF = __uint_as_float(INFB);

    const float* mrow = masked + (size_t)row * NN;
    const float* drow = distance + ((size_t)b * NN + current[row]) * NN;

    float v[16];
#pragma unroll
    for (int j = 0; j < 16; j++) {
        int n = lane + 32 * j;
        float val = FINF;
        if (n < NN) {
            float m = __ldg(mrow + n);
            if (m > -1e37f) val = __ldg(drow + n);
        }
        v[j] = val;
    }

    float lv = v[0]; int lj = 0;
#pragma unroll
    for (int j = 1; j < 16; j++)
        if (v[j] < lv) { lv = v[j]; lj = j; }

    int sel[NK];
#pragma unroll
    for (int k = 0; k < NK; k++) {
        uint32_t lvb = __float_as_uint(lv);
        uint32_t gvb = __reduce_min_sync(0xffffffffu, lvb);
        uint32_t myn = (lvb == gvb) ? (uint32_t)(lane + 32 * lj) : 0xffffffffu;
        uint32_t gn  = __reduce_min_sync(0xffffffffu, myn);
        if (gvb < INFB) {
            sel[k] = (int)gn;
            if (myn == gn) {
#pragma unroll
                for (int j = 0; j < 16; j++)
                    if (j == lj) v[j] = FINF;
                lv = v[0]; lj = 0;
#pragma unroll
                for (int j = 1; j < 16; j++)
                    if (v[j] < lv) { lv = v[j]; lj = j; }
            }
        } else {
            sel[k] = NN;
        }
    }

    // pad-avg mean over selected rows (raw enc, then tf32-round)
    float4 acc = make_float4(0.f, 0.f, 0.f, 0.f);
    int cnt = 0;
#pragma unroll
    for (int k = 0; k < NK; k++) {
        if (sel[k] < NN) {
            cnt++;
            float4 e = *(const float4*)(enc + ((size_t)b * NN + sel[k]) * NE + lane * 4);
            acc.x += e.x; acc.y += e.y; acc.z += e.z; acc.w += e.w;
        }
    }
    float cf = (cnt > 0) ? (float)cnt : 1.0f;
    float4 mean = make_float4(f2tf_f(acc.x / cf), f2tf_f(acc.y / cf),
                              f2tf_f(acc.z / cf), f2tf_f(acc.w / cf));
    *(float4*)(g_mean + (size_t)row * NE + lane * 4) = mean;

#pragma unroll
    for (int k = 0; k < NK; k++)
        if (lane == k) g_sel[(size_t)row * NK + k] = sel[k];
}

// ---------------------------------------------------------------------------
// Fused MLP: out[m,0:128] = (relu(A[m,:] @ w1^T + b1)) @ w2^T + b2
// A rows gathered on the fly from g_encr / g_mean via smem pointer table.
// Per block: 128-row M-stripe. Loop 5 H1-blocks of 128:
//   GEMM1 (K=1280) -> relu+round -> smem h_s -> GEMM2 partial into out acc.
// tf32 mma.sync m16n8k8, 8 warps, warp tile 64x32, 3-stage cp.async.
// ---------------------------------------------------------------------------
#define AW   36                 // row stride (words): 32 + 4 pad
#define STW  (128 * AW)         // words per operand stage (4608)
#define HW   132                // h_s row stride (words)
#define SM_H      (6 * STW)                 // word offset of h_s
#define SM_PTRB   ((6 * STW + 128 * HW) * 4)  // byte offset of ptr table
#define SMEMSZ    (SM_PTRB + 128 * NK * 8)    // 188416 bytes

__device__ __forceinline__ void cp16(uint32_t s, const void* g) {
    asm volatile("cp.async.cg.shared.global [%0], [%1], 16;\n" :: "r"(s), "l"(g));
}
__device__ __forceinline__ void cpcommit() {
    asm volatile("cp.async.commit_group;\n" ::);
}
template<int Npend> __device__ __forceinline__ void cpwait() {
    asm volatile("cp.async.wait_group %0;\n" :: "n"(Npend));
}
#define MMA_TF32(acc, a, b)                                                  \
    asm volatile(                                                            \
        "mma.sync.aligned.m16n8k8.row.col.f32.tf32.tf32.f32 "                \
        "{%0,%1,%2,%3}, {%4,%5,%6,%7}, {%8,%9}, {%0,%1,%2,%3};\n"            \
        : "+f"(acc[0]), "+f"(acc[1]), "+f"(acc[2]), "+f"(acc[3])             \
        : "r"(a[0]), "r"(a[1]), "r"(a[2]), "r"(a[3]), "r"(b[0]), "r"(b[1]))

__global__ void __launch_bounds__(256) mlp_kernel(
    const float* __restrict__ b1, const float* __restrict__ b2,
    float* __restrict__ out)
{
    extern __shared__ char smem[];
    float*    sf   = (float*)smem;
    uint64_t* sPtr = (uint64_t*)(smem + SM_PTRB);
    const uint32_t sb = (uint32_t)__cvta_generic_to_shared(smem);

    const int t    = threadIdx.x;
    const int lane = t & 31;
    const int w    = t >> 5;
    const int wm   = w >> 2;        // 0..1
    const int wn   = w & 3;         // 0..3
    const int tr   = t >> 3;        // 0..31
    const int tc   = (t & 7) * 4;   // 0,4,..28
    const int m0   = blockIdx.x * 128;

    // Build gather pointer table: sPtr[r*10+ks] -> 128-float source row
    for (int i = t; i < 128 * NK; i += 256) {
        int r = i / NK, ks = i % NK;
        int m = m0 + r;
        int s = g_sel[(size_t)m * NK + ks];
        const float* p = (s < NN)
            ? (g_encr + ((size_t)(m / NR) * NN + s) * NE)
            : (g_mean + (size_t)m * NE);
        sPtr[i] = (uint64_t)p;
    }
    __syncthreads();

    float oacc[4][4][4];
#pragma unroll
    for (int i = 0; i < 4; i++)
#pragma unroll
        for (int j = 0; j < 4; j++)
#pragma unroll
            for (int q = 0; q < 4; q++) oacc[i][j][q] = 0.f;

    const uint32_t* Hs = (const uint32_t*)(sf + SM_H);

    for (int nb = 0; nb < 5; nb++) {
        // ------------- GEMM1: hacc = A(gather) @ w1_nb^T, K = 1280 ---------
        float hacc[4][4][4];
#pragma unroll
        for (int i = 0; i < 4; i++)
#pragma unroll
            for (int j = 0; j < 4; j++)
#pragma unroll
                for (int q = 0; q < 4; q++) hacc[i][j][q] = 0.f;

        auto issueAB = [&](int it) {
            const int k0 = it * 32;
            const int ks = k0 >> 7;
            const int e0 = (k0 & 127) + tc;
            const uint32_t stg = sb + (uint32_t)(it % 3) * (2 * STW * 4);
#pragma unroll
            for (int p = 0; p < 4; p++) {
                const int r = tr + p * 32;
                const float* pa = (const float*)sPtr[r * NK + ks] + e0;
                cp16(stg + (uint32_t)(r * AW + tc) * 4, pa);
                const float* pw = g_w1 + (size_t)(nb * 128 + r) * NKE + k0 + tc;
                cp16(stg + (uint32_t)(STW + r * AW + tc) * 4, pw);
            }
        };

        issueAB(0); cpcommit();
        issueAB(1); cpcommit();

        constexpr int NT = NKE / 32;   // 40
        for (int it = 0; it < NT; it++) {
            cpwait<1>();
            __syncthreads();
            if (it + 2 < NT) issueAB(it + 2);
            cpcommit();

            const uint32_t* As = (const uint32_t*)(sf + (it % 3) * 2 * STW);
            const uint32_t* Bs = As + STW;
#pragma unroll
            for (int kk = 0; kk < 32; kk += 8) {
                const int kc = kk + (lane & 3);
                uint32_t a[4][4];
#pragma unroll
                for (int mt = 0; mt < 4; mt++) {
                    const int mr = wm * 64 + mt * 16 + (lane >> 2);
                    a[mt][0] = As[mr * AW + kc];
                    a[mt][1] = As[(mr + 8) * AW + kc];
                    a[mt][2] = As[mr * AW + kc + 4];
                    a[mt][3] = As[(mr + 8) * AW + kc + 4];
                }
                uint32_t bb[4][2];
#pragma unroll
                for (int nt = 0; nt < 4; nt++) {
                    const int nc = wn * 32 + nt * 8 + (lane >> 2);
                    bb[nt][0] = Bs[nc * AW + kc];
                    bb[nt][1] = Bs[nc * AW + kc + 4];
                }
#pragma unroll
                for (int mt = 0; mt < 4; mt++)
#pragma unroll
                    for (int nt = 0; nt < 4; nt++)
                        MMA_TF32(hacc[mt][nt], a[mt], bb[nt]);
            }
            __syncthreads();
        }

        // ------------- h epilogue: bias + relu + round -> smem h_s ---------
#pragma unroll
        for (int mt = 0; mt < 4; mt++) {
#pragma unroll
            for (int nt = 0; nt < 4; nt++) {
                const int mr = wm * 64 + mt * 16 + (lane >> 2);
                const int nc = wn * 32 + nt * 8 + (lane & 3) * 2;
                const float bx = __ldg(b1 + nb * 128 + nc);
                const float by = __ldg(b1 + nb * 128 + nc + 1);
                float2 r0, r1;
                r0.x = f2tf_f(fmaxf(hacc[mt][nt][0] + bx, 0.f));
                r0.y = f2tf_f(fmaxf(hacc[mt][nt][1] + by, 0.f));
                r1.x = f2tf_f(fmaxf(hacc[mt][nt][2] + bx, 0.f));
                r1.y = f2tf_f(fmaxf(hacc[mt][nt][3] + by, 0.f));
                *(float2*)(sf + SM_H + mr * HW + nc)       = r0;
                *(float2*)(sf + SM_H + (mr + 8) * HW + nc) = r1;
            }
        }
        __syncthreads();

        // ------------- GEMM2 partial: oacc += h_s @ w2_nb^T, K = 128 -------
        auto issueW2 = [&](int it) {
            const int kk0 = it * 32;
            const uint32_t stg = sb + (uint32_t)((it % 3) * 2 * STW + STW) * 4;
#pragma unroll
            for (int p = 0; p < 4; p++) {
                const int r = tr + p * 32;
                cp16(stg + (uint32_t)(r * AW + tc) * 4,
                     g_w2 + (size_t)r * NH1 + nb * 128 + kk0 + tc);
            }
        };

        issueW2(0); cpcommit();
        issueW2(1); cpcommit();

        for (int it = 0; it < 4; it++) {
            cpwait<1>();
            __syncthreads();
            if (it + 2 < 4) issueW2(it + 2);
            cpcommit();

            const uint32_t* Bs = (const uint32_t*)(sf + (it % 3) * 2 * STW) + STW;
#pragma unroll
            for (int kk = 0; kk < 32; kk += 8) {
                const int kcH = it * 32 + kk + (lane & 3);
                const int kc  = kk + (lane & 3);
                uint32_t a[4][4];
#pragma unroll
                for (int mt = 0; mt < 4; mt++) {
                    const int mr = wm * 64 + mt * 16 + (lane >> 2);
                    a[mt][0] = Hs[mr * HW + kcH];
                    a[mt][1] = Hs[(mr + 8) * HW + kcH];
                    a[mt][2] = Hs[mr * HW + kcH + 4];
                    a[mt][3] = Hs[(mr + 8) * HW + kcH + 4];
                }
                uint32_t bb[4][2];
#pragma unroll
                for (int nt = 0; nt < 4; nt++) {
                    const int nc = wn * 32 + nt * 8 + (lane >> 2);
                    bb[nt][0] = Bs[nc * AW + kc];
                    bb[nt][1] = Bs[nc * AW + kc + 4];
                }
#pragma unroll
                for (int mt = 0; mt < 4; mt++)
#pragma unroll
                    for (int nt = 0; nt < 4; nt++)
                        MMA_TF32(oacc[mt][nt], a[mt], bb[nt]);
            }
            __syncthreads();
        }
    }

    // ------------- final epilogue: + b2 -> global out ----------------------
#pragma unroll
    for (int mt = 0; mt < 4; mt++) {
#pragma unroll
        for (int nt = 0; nt < 4; nt++) {
            const int mr = m0 + wm * 64 + mt * 16 + (lane >> 2);
            const int nc = wn * 32 + nt * 8 + (lane & 3) * 2;
            const float bx = __ldg(b2 + nc);
            const float by = __ldg(b2 + nc + 1);
            float2 r0 = make_float2(oacc[mt][nt][0] + bx, oacc[mt][nt][1] + by);
            float2 r1 = make_float2(oacc[mt][nt][2] + bx, oacc[mt][nt][3] + by);
            *(float2*)(out + (size_t)mr * NE + nc)       = r0;
            *(float2*)(out + (size_t)(mr + 8) * NE + nc) = r1;
        }
    }
}

// ---------------------------------------------------------------------------
extern "C" void kernel_launch(void* const* d_in, const int* in_sizes, int n_in,
                              void* d_out, int out_size)
{
    const int*   current  = (const int*)  d_in[0];
    const float* distance = (const float*)d_in[1];
    const float* masked   = (const float*)d_in[2];
    const float* enc      = (const float*)d_in[3];
    const float* w1       = (const float*)d_in[4];
    const float* b1       = (const float*)d_in[5];
    const float* w2       = (const float*)d_in[6];
    const float* b2       = (const float*)d_in[7];
    float* out = (float*)d_out;

    cudaFuncSetAttribute(mlp_kernel,
                         cudaFuncAttributeMaxDynamicSharedMemorySize, SMEMSZ);

    cvt_kernel<<<(NB * NN * NE + 255) / 256, 256>>>(enc, w1, w2);
    prep_kernel<<<NM / 4, 128>>>(current, distance, masked, enc);
    mlp_kernel<<<NM / 128, 256, SMEMSZ>>>(b1, b2, out);
}

// round 6
// speedup vs baseline: 1.9432x; 1.9432x over previous
#include <cuda_runtime.h>
#include <cuda_fp16.h>
#include <cstdint>
#include <cstddef>

// Problem constants
#define NB  128
#define NR  500
#define NN  500
#define NK  10
#define NE  128
#define NH1 640
#define NKE 1280
#define NM  (NB * NR)       // 64000 rows

// Scratch (static device arrays)
__device__ __half g_ench[(size_t)NB * NN * NE];  // fp16 enc (16.4 MB, L2-resident)
__device__ __half g_meanh[(size_t)NM * NE];      // fp16 pad mean (16.4 MB)
__device__ int    g_sel[(size_t)NM * NK];        // selected node ids
__device__ __half g_w1h[NH1 * NKE];              // fp16 w1 (1.6 MB)
__device__ __half g_w2h[NE * NH1];               // fp16 w2
__device__ __half g_hh[(size_t)NM * NH1];        // fp16 hidden (81.9 MB)

// ---------------------------------------------------------------------------
// Kernel 0: round enc, w1, w2 to fp16
// ---------------------------------------------------------------------------
__global__ void __launch_bounds__(256) cvt_kernel(
    const float* __restrict__ enc,
    const float* __restrict__ w1, const float* __restrict__ w2)
{
    int i = blockIdx.x * 256 + threadIdx.x;
    if (i < NB * NN * NE) g_ench[i] = __float2half_rn(enc[i]);
    if (i < NH1 * NKE)    g_w1h[i]  = __float2half_rn(w1[i]);
    if (i < NE * NH1)     g_w2h[i]  = __float2half_rn(w2[i]);
}

// ---------------------------------------------------------------------------
// Kernel 1: top-K nearest unvisited -> g_sel; pad mean -> g_meanh
// One warp per (b, r) row. 4 warps / block.
// ---------------------------------------------------------------------------
__global__ void __launch_bounds__(128) prep_kernel(
    const int*   __restrict__ current,
    const float* __restrict__ distance,
    const float* __restrict__ masked,
    const float* __restrict__ enc)
{
    const int row  = blockIdx.x * 4 + (threadIdx.x >> 5);
    const int lane = threadIdx.x & 31;
    const int b    = row / NR;
    const uint32_t INFB = 0x7f800000u;
    const float FINF = __uint_as_float(INFB);

    const float* mrow = masked + (size_t)row * NN;
    const float* drow = distance + ((size_t)b * NN + current[row]) * NN;

    float v[16];
#pragma unroll
    for (int j = 0; j < 16; j++) {
        int n = lane + 32 * j;
        float val = FINF;
        if (n < NN) {
            float m = __ldg(mrow + n);
            if (m > -1e37f) val = __ldg(drow + n);
        }
        v[j] = val;
    }

    float lv = v[0]; int lj = 0;
#pragma unroll
    for (int j = 1; j < 16; j++)
        if (v[j] < lv) { lv = v[j]; lj = j; }

    int sel[NK];
#pragma unroll
    for (int k = 0; k < NK; k++) {
        uint32_t lvb = __float_as_uint(lv);
        uint32_t gvb = __reduce_min_sync(0xffffffffu, lvb);
        uint32_t myn = (lvb == gvb) ? (uint32_t)(lane + 32 * lj) : 0xffffffffu;
        uint32_t gn  = __reduce_min_sync(0xffffffffu, myn);
        if (gvb < INFB) {
            sel[k] = (int)gn;
            if (myn == gn) {
#pragma unroll
                for (int j = 0; j < 16; j++)
                    if (j == lj) v[j] = FINF;
                lv = v[0]; lj = 0;
#pragma unroll
                for (int j = 1; j < 16; j++)
                    if (v[j] < lv) { lv = v[j]; lj = j; }
            }
        } else {
            sel[k] = NN;
        }
    }

    // pad-avg mean over selected rows (fp32 math, then fp16 round)
    float4 acc = make_float4(0.f, 0.f, 0.f, 0.f);
    int cnt = 0;
#pragma unroll
    for (int k = 0; k < NK; k++) {
        if (sel[k] < NN) {
            cnt++;
            float4 e = *(const float4*)(enc + ((size_t)b * NN + sel[k]) * NE + lane * 4);
            acc.x += e.x; acc.y += e.y; acc.z += e.z; acc.w += e.w;
        }
    }
    float cf = (cnt > 0) ? (float)cnt : 1.0f;
    __half2 m01 = __floats2half2_rn(acc.x / cf, acc.y / cf);
    __half2 m23 = __floats2half2_rn(acc.z / cf, acc.w / cf);
    *(__half2*)(g_meanh + (size_t)row * NE + lane * 4)     = m01;
    *(__half2*)(g_meanh + (size_t)row * NE + lane * 4 + 2) = m23;

#pragma unroll
    for (int k = 0; k < NK; k++)
        if (lane == k) g_sel[(size_t)row * NK + k] = sel[k];
}

// ---------------------------------------------------------------------------
// fp16 mma.sync m16n8k16 GEMMs, cp.async 3-stage, block 128x128, 8 warps,
// warp tile 64x32. BK=32 halfs; smem rows 40 halfs (80B, conflict-free).
// ---------------------------------------------------------------------------
#define AWH   40                       // smem row stride in halfs
#define OPB   (128 * AWH * 2)          // bytes per operand stage (10240)
#define STGB  (2 * OPB)                // bytes per stage (A+B)
#define G1_SMEM (3 * STGB + 128 * NK * 8)   // 61440 + 10240 = 71680
#define G2_SMEM (3 * STGB)                  // 61440

__device__ __forceinline__ void cp16(uint32_t s, const void* g) {
    asm volatile("cp.async.cg.shared.global [%0], [%1], 16;\n" :: "r"(s), "l"(g));
}
__device__ __forceinline__ void cpcommit() {
    asm volatile("cp.async.commit_group;\n" ::);
}
template<int Npend> __device__ __forceinline__ void cpwait() {
    asm volatile("cp.async.wait_group %0;\n" :: "n"(Npend));
}
#define MMA_F16(acc, a, b)                                                   \
    asm volatile(                                                            \
        "mma.sync.aligned.m16n8k16.row.col.f32.f16.f16.f32 "                 \
        "{%0,%1,%2,%3}, {%4,%5,%6,%7}, {%8,%9}, {%0,%1,%2,%3};\n"            \
        : "+f"(acc[0]), "+f"(acc[1]), "+f"(acc[2]), "+f"(acc[3])             \
        : "r"(a[0]), "r"(a[1]), "r"(a[2]), "r"(a[3]), "r"(b[0]), "r"(b[1]))

// GEMM1: g_hh[m, n0:n0+128] = relu(gatherA[m,:] @ w1^T + b1), Kk=1280
__global__ void __launch_bounds__(256, 2) gemm1_kernel(const float* __restrict__ b1)
{
    extern __shared__ char smem[];
    uint64_t* sPtr = (uint64_t*)(smem + 3 * STGB);
    const uint32_t sb = (uint32_t)__cvta_generic_to_shared(smem);

    const int t    = threadIdx.x;
    const int lane = t & 31;
    const int w    = t >> 5;
    const int wm   = w >> 2;        // 0..1
    const int wn   = w & 3;         // 0..3
    const int m0   = blockIdx.y * 128;
    const int n0   = blockIdx.x * 128;

    // Build per-row gather pointers: sPtr[r*10+ks]
    for (int i = t; i < 128 * NK; i += 256) {
        int r = i / NK, ks = i % NK;
        int m = m0 + r;
        int s = g_sel[(size_t)m * NK + ks];
        const __half* p = (s < NN)
            ? (g_ench + ((size_t)(m / NR) * NN + s) * NE)
            : (g_meanh + (size_t)m * NE);
        sPtr[i] = (uint64_t)p;
    }
    __syncthreads();

    float acc[4][4][4];
#pragma unroll
    for (int i = 0; i < 4; i++)
#pragma unroll
        for (int j = 0; j < 4; j++)
#pragma unroll
            for (int q = 0; q < 4; q++) acc[i][j][q] = 0.f;

    auto issue = [&](int it) {
        const int k0 = it * 32;
        const int ks = k0 >> 7;
        const int ko = k0 & 127;
        const uint32_t stg = sb + (uint32_t)(it % 3) * STGB;
#pragma unroll
        for (int i = 0; i < 2; i++) {
            int c = t + i * 256;          // 0..511 (A chunks); same id for B
            int r = c >> 2, c16 = c & 3;
            const __half* pa = (const __half*)sPtr[r * NK + ks] + ko + c16 * 8;
            cp16(stg + (uint32_t)(r * 80 + c16 * 16), pa);
            const __half* pw = g_w1h + (size_t)(n0 + r) * NKE + k0 + c16 * 8;
            cp16(stg + (uint32_t)(OPB + r * 80 + c16 * 16), pw);
        }
    };

    issue(0); cpcommit();
    issue(1); cpcommit();

    constexpr int NT = NKE / 32;   // 40
    for (int it = 0; it < NT; it++) {
        cpwait<1>();
        __syncthreads();
        if (it + 2 < NT) issue(it + 2);
        cpcommit();

        const __half* As = (const __half*)(smem + (it % 3) * STGB);
        const __half* Bs = As + OPB / 2;
#pragma unroll
        for (int kk = 0; kk < 32; kk += 16) {
            const int kc = kk + 2 * (lane & 3);
            uint32_t a[4][4];
#pragma unroll
            for (int mt = 0; mt < 4; mt++) {
                const int mr = wm * 64 + mt * 16 + (lane >> 2);
                a[mt][0] = *(const uint32_t*)(As + mr * AWH + kc);
                a[mt][1] = *(const uint32_t*)(As + (mr + 8) * AWH + kc);
                a[mt][2] = *(const uint32_t*)(As + mr * AWH + kc + 8);
                a[mt][3] = *(const uint32_t*)(As + (mr + 8) * AWH + kc + 8);
            }
            uint32_t bb[4][2];
#pragma unroll
            for (int nt = 0; nt < 4; nt++) {
                const int nc = wn * 32 + nt * 8 + (lane >> 2);
                bb[nt][0] = *(const uint32_t*)(Bs + nc * AWH + kc);
                bb[nt][1] = *(const uint32_t*)(Bs + nc * AWH + kc + 8);
            }
#pragma unroll
            for (int mt = 0; mt < 4; mt++)
#pragma unroll
                for (int nt = 0; nt < 4; nt++)
                    MMA_F16(acc[mt][nt], a[mt], bb[nt]);
        }
        __syncthreads();
    }

    // Epilogue: bias + relu -> fp16 -> g_hh
#pragma unroll
    for (int mt = 0; mt < 4; mt++) {
#pragma unroll
        for (int nt = 0; nt < 4; nt++) {
            const int mr = m0 + wm * 64 + mt * 16 + (lane >> 2);
            const int nc = n0 + wn * 32 + nt * 8 + (lane & 3) * 2;
            const float bx = __ldg(b1 + nc);
            const float by = __ldg(b1 + nc + 1);
            __half2 h0 = __floats2half2_rn(fmaxf(acc[mt][nt][0] + bx, 0.f),
                                           fmaxf(acc[mt][nt][1] + by, 0.f));
            __half2 h1 = __floats2half2_rn(fmaxf(acc[mt][nt][2] + bx, 0.f),
                                           fmaxf(acc[mt][nt][3] + by, 0.f));
            *(__half2*)(g_hh + (size_t)mr * NH1 + nc)       = h0;
            *(__half2*)(g_hh + (size_t)(mr + 8) * NH1 + nc) = h1;
        }
    }
}

// GEMM2: out[m, 0:128] = g_hh[m,:] @ w2^T + b2, Kk=640
__global__ void __launch_bounds__(256, 2) gemm2_kernel(
    const float* __restrict__ b2, float* __restrict__ out)
{
    extern __shared__ char smem[];
    const uint32_t sb = (uint32_t)__cvta_generic_to_shared(smem);

    const int t    = threadIdx.x;
    const int lane = t & 31;
    const int w    = t >> 5;
    const int wm   = w >> 2;
    const int wn   = w & 3;
    const int m0   = blockIdx.x * 128;

    float acc[4][4][4];
#pragma unroll
    for (int i = 0; i < 4; i++)
#pragma unroll
        for (int j = 0; j < 4; j++)
#pragma unroll
            for (int q = 0; q < 4; q++) acc[i][j][q] = 0.f;

    auto issue = [&](int it) {
        const int k0 = it * 32;
        const uint32_t stg = sb + (uint32_t)(it % 3) * STGB;
#pragma unroll
        for (int i = 0; i < 2; i++) {
            int c = t + i * 256;
            int r = c >> 2, c16 = c & 3;
            cp16(stg + (uint32_t)(r * 80 + c16 * 16),
                 g_hh + (size_t)(m0 + r) * NH1 + k0 + c16 * 8);
            cp16(stg + (uint32_t)(OPB + r * 80 + c16 * 16),
                 g_w2h + (size_t)r * NH1 + k0 + c16 * 8);
        }
    };

    issue(0); cpcommit();
    issue(1); cpcommit();

    constexpr int NT = NH1 / 32;   // 20
    for (int it = 0; it < NT; it++) {
        cpwait<1>();
        __syncthreads();
        if (it + 2 < NT) issue(it + 2);
        cpcommit();

        const __half* As = (const __half*)(smem + (it % 3) * STGB);
        const __half* Bs = As + OPB / 2;
#pragma unroll
        for (int kk = 0; kk < 32; kk += 16) {
            const int kc = kk + 2 * (lane & 3);
            uint32_t a[4][4];
#pragma unroll
            for (int mt = 0; mt < 4; mt++) {
                const int mr = wm * 64 + mt * 16 + (lane >> 2);
                a[mt][0] = *(const uint32_t*)(As + mr * AWH + kc);
                a[mt][1] = *(const uint32_t*)(As + (mr + 8) * AWH + kc);
                a[mt][2] = *(const uint32_t*)(As + mr * AWH + kc + 8);
                a[mt][3] = *(const uint32_t*)(As + (mr + 8) * AWH + kc + 8);
            }
            uint32_t bb[4][2];
#pragma unroll
            for (int nt = 0; nt < 4; nt++) {
                const int nc = wn * 32 + nt * 8 + (lane >> 2);
                bb[nt][0] = *(const uint32_t*)(Bs + nc * AWH + kc);
                bb[nt][1] = *(const uint32_t*)(Bs + nc * AWH + kc + 8);
            }
#pragma unroll
            for (int mt = 0; mt < 4; mt++)
#pragma unroll
                for (int nt = 0; nt < 4; nt++)
                    MMA_F16(acc[mt][nt], a[mt], bb[nt]);
        }
        __syncthreads();
    }

#pragma unroll
    for (int mt = 0; mt < 4; mt++) {
#pragma unroll
        for (int nt = 0; nt < 4; nt++) {
            const int mr = m0 + wm * 64 + mt * 16 + (lane >> 2);
            const int nc = wn * 32 + nt * 8 + (lane & 3) * 2;
            const float bx = __ldg(b2 + nc);
            const float by = __ldg(b2 + nc + 1);
            float2 r0 = make_float2(acc[mt][nt][0] + bx, acc[mt][nt][1] + by);
            float2 r1 = make_float2(acc[mt][nt][2] + bx, acc[mt][nt][3] + by);
            *(float2*)(out + (size_t)mr * NE + nc)       = r0;
            *(float2*)(out + (size_t)(mr + 8) * NE + nc) = r1;
        }
    }
}

// ---------------------------------------------------------------------------
extern "C" void kernel_launch(void* const* d_in, const int* in_sizes, int n_in,
                              void* d_out, int out_size)
{
    const int*   current  = (const int*)  d_in[0];
    const float* distance = (const float*)d_in[1];
    const float* masked   = (const float*)d_in[2];
    const float* enc      = (const float*)d_in[3];
    const float* w1       = (const float*)d_in[4];
    const float* b1       = (const float*)d_in[5];
    const float* w2       = (const float*)d_in[6];
    const float* b2       = (const float*)d_in[7];
    float* out = (float*)d_out;

    cudaFuncSetAttribute(gemm1_kernel,
                         cudaFuncAttributeMaxDynamicSharedMemorySize, G1_SMEM);
    cudaFuncSetAttribute(gemm2_kernel,
                         cudaFuncAttributeMaxDynamicSharedMemorySize, G2_SMEM);

    cvt_kernel<<<(NB * NN * NE + 255) / 256, 256>>>(enc, w1, w2);
    prep_kernel<<<NM / 4, 128>>>(current, distance, masked, enc);
    gemm1_kernel<<<dim3(NH1 / 128, NM / 128), 256, G1_SMEM>>>(b1);
    gemm2_kernel<<<NM / 128, 256, G2_SMEM>>>(b2, out);
}